// round 3
// baseline (speedup 1.0000x reference)
#include <cuda_runtime.h>
#include <cuda_bf16.h>
#include <cstdint>

// Problem constants (fixed shapes from reference)
#define PB 4
#define PT 2048
#define PD 1024
#define PH 16
#define PDH 64
#define PM (PB*PT)          // 8192 rows
#define PN 1024             // H*Dh == D
#define PK 1024

// ---------------- scratch (device globals; no allocations allowed) ----------
__device__ float g_Q [PM*PN];
__device__ float g_K [PM*PN];
__device__ float g_V [PM*PN];
__device__ float g_OH[PM*PN];
__device__ float g_WOt[PD*PN];

// ---------------- WO transpose: [H][D][Dh] -> [D][H*Dh] ---------------------
__global__ void transpose_wo(const float* __restrict__ WO, float* __restrict__ WOt) {
    int idx = blockIdx.x * 256 + threadIdx.x;     // H*D*Dh = 1,048,576 threads
    int k = idx & 63;
    int d = (idx >> 6) & 1023;
    int h = idx >> 16;
    WOt[d * 1024 + h * 64 + k] = WO[idx];
}

// ---------------- NT GEMM + bias: C[m][n] = sum_k A[m][k]*B[n][k] + bias[n] -
// M=8192, N=1024, K=1024 fixed. 128x128 block tile, BK=16, 8x8 per thread.
__global__ __launch_bounds__(256)
void gemm_nt_bias(const float* __restrict__ A, const float* __restrict__ B,
                  const float* __restrict__ bias, float* __restrict__ C) {
    __shared__ float As[16][132];   // transposed tiles: As[k][m]
    __shared__ float Bs[16][132];

    const int tid = threadIdx.x;
    const int tx = tid & 15, ty = tid >> 4;
    const float* Ag = A + (size_t)blockIdx.y * 128 * PK;
    const float* Bg = B + (size_t)blockIdx.x * 128 * PK;

    const int lr = tid >> 1;           // 0..127
    const int lc = (tid & 1) * 8;      // 0 or 8

    float acc[8][8];
#pragma unroll
    for (int i = 0; i < 8; i++)
#pragma unroll
        for (int j = 0; j < 8; j++) acc[i][j] = 0.f;

    for (int k0 = 0; k0 < PK; k0 += 16) {
        float4 a0 = *(const float4*)(Ag + (size_t)lr * PK + k0 + lc);
        float4 a1 = *(const float4*)(Ag + (size_t)lr * PK + k0 + lc + 4);
        float4 b0 = *(const float4*)(Bg + (size_t)lr * PK + k0 + lc);
        float4 b1 = *(const float4*)(Bg + (size_t)lr * PK + k0 + lc + 4);
        __syncthreads();   // previous compute done before overwriting tiles
        As[lc+0][lr] = a0.x; As[lc+1][lr] = a0.y; As[lc+2][lr] = a0.z; As[lc+3][lr] = a0.w;
        As[lc+4][lr] = a1.x; As[lc+5][lr] = a1.y; As[lc+6][lr] = a1.z; As[lc+7][lr] = a1.w;
        Bs[lc+0][lr] = b0.x; Bs[lc+1][lr] = b0.y; Bs[lc+2][lr] = b0.z; Bs[lc+3][lr] = b0.w;
        Bs[lc+4][lr] = b1.x; Bs[lc+5][lr] = b1.y; Bs[lc+6][lr] = b1.z; Bs[lc+7][lr] = b1.w;
        __syncthreads();
#pragma unroll
        for (int kk = 0; kk < 16; kk++) {
            float ra[8], rb[8];
            *(float4*)&ra[0] = *(const float4*)&As[kk][4 * ty];
            *(float4*)&ra[4] = *(const float4*)&As[kk][64 + 4 * ty];
            *(float4*)&rb[0] = *(const float4*)&Bs[kk][4 * tx];
            *(float4*)&rb[4] = *(const float4*)&Bs[kk][64 + 4 * tx];
#pragma unroll
            for (int i = 0; i < 8; i++)
#pragma unroll
                for (int j = 0; j < 8; j++) acc[i][j] += ra[i] * rb[j];
        }
    }

    const int row0 = blockIdx.y * 128;
    const int col0 = blockIdx.x * 128;
    float4 bia = *(const float4*)(bias + col0 + 4 * tx);
    float4 bib = *(const float4*)(bias + col0 + 64 + 4 * tx);
#pragma unroll
    for (int i = 0; i < 8; i++) {
        int r = row0 + ((i < 4) ? (4 * ty + i) : (64 + 4 * ty + (i - 4)));
        float4 v0 = make_float4(acc[i][0] + bia.x, acc[i][1] + bia.y,
                                acc[i][2] + bia.z, acc[i][3] + bia.w);
        float4 v1 = make_float4(acc[i][4] + bib.x, acc[i][5] + bib.y,
                                acc[i][6] + bib.z, acc[i][7] + bib.w);
        *(float4*)(C + (size_t)r * PN + col0 + 4 * tx)      = v0;
        *(float4*)(C + (size_t)r * PN + col0 + 64 + 4 * tx) = v1;
    }
}

// ---------------- flash attention: per (b,h), 64-query x 64-key tiles -------
// Q/K/V/OH are [8192][1024] with column offset h*64 (layout [B,T,H,Dh]).
#define LDP 68
__global__ __launch_bounds__(256)
void flash_kernel(const float* __restrict__ Qg, const float* __restrict__ Kg,
                  const float* __restrict__ Vg, float* __restrict__ OHg) {
    extern __shared__ float sm[];
    float* Qt  = sm;               // [64][LDP]  transposed: Qt[k][r]
    float* KPt = sm + 64 * LDP;    // K transposed [k][c], reused as P^T [c][r]
    float* Vs  = sm + 2 * 64 * LDP; // [c][LDP]  natural

    const int tid = threadIdx.x;
    const int tx = tid & 15, ty = tid >> 4;
    const int q0 = blockIdx.x * 64;
    const int bh = blockIdx.y;
    const int b = bh >> 4, h = bh & 15;
    const size_t base = (size_t)b * (PT * PN) + (size_t)h * PDH;

    const int lr  = tid >> 2;       // 0..63
    const int lc4 = tid & 3;        // float4 slot base

    // load Q tile transposed, pre-scaled by 1/sqrt(Dh)
#pragma unroll
    for (int u = 0; u < 4; u++) {
        int c = (lc4 + 4 * u) * 4;
        float4 v = *(const float4*)(Qg + base + (size_t)(q0 + lr) * PN + c);
        Qt[(c + 0) * LDP + lr] = v.x * 0.125f;
        Qt[(c + 1) * LDP + lr] = v.y * 0.125f;
        Qt[(c + 2) * LDP + lr] = v.z * 0.125f;
        Qt[(c + 3) * LDP + lr] = v.w * 0.125f;
    }

    float m_r[4], l_r[4], o[4][4];
#pragma unroll
    for (int i = 0; i < 4; i++) {
        m_r[i] = -1e30f; l_r[i] = 0.f;
#pragma unroll
        for (int j = 0; j < 4; j++) o[i][j] = 0.f;
    }

    for (int c0 = 0; c0 < PT; c0 += 64) {
        __syncthreads();   // previous PV done (and Q-store visible on iter 0)
#pragma unroll
        for (int u = 0; u < 4; u++) {
            int c = (lc4 + 4 * u) * 4;
            float4 kv = *(const float4*)(Kg + base + (size_t)(c0 + lr) * PN + c);
            KPt[(c + 0) * LDP + lr] = kv.x;
            KPt[(c + 1) * LDP + lr] = kv.y;
            KPt[(c + 2) * LDP + lr] = kv.z;
            KPt[(c + 3) * LDP + lr] = kv.w;
            float4 vv = *(const float4*)(Vg + base + (size_t)(c0 + lr) * PN + c);
            *(float4*)&Vs[lr * LDP + c] = vv;
        }
        __syncthreads();

        // S tile: s[i][j] = sum_k Qt[k][4ty+i] * KPt[k][4tx+j]
        float s[4][4];
#pragma unroll
        for (int i = 0; i < 4; i++)
#pragma unroll
            for (int j = 0; j < 4; j++) s[i][j] = 0.f;
#pragma unroll
        for (int kk = 0; kk < 64; kk++) {
            float4 qa = *(const float4*)&Qt[kk * LDP + 4 * ty];
            float4 kb = *(const float4*)&KPt[kk * LDP + 4 * tx];
            s[0][0] += qa.x*kb.x; s[0][1] += qa.x*kb.y; s[0][2] += qa.x*kb.z; s[0][3] += qa.x*kb.w;
            s[1][0] += qa.y*kb.x; s[1][1] += qa.y*kb.y; s[1][2] += qa.y*kb.z; s[1][3] += qa.y*kb.w;
            s[2][0] += qa.z*kb.x; s[2][1] += qa.z*kb.y; s[2][2] += qa.z*kb.z; s[2][3] += qa.z*kb.w;
            s[3][0] += qa.w*kb.x; s[3][1] += qa.w*kb.y; s[3][2] += qa.w*kb.z; s[3][3] += qa.w*kb.w;
        }

        // online softmax (rows 4ty+i; 16-lane row groups share stats via shfl)
#pragma unroll
        for (int i = 0; i < 4; i++) {
            float rm = fmaxf(fmaxf(s[i][0], s[i][1]), fmaxf(s[i][2], s[i][3]));
            rm = fmaxf(rm, __shfl_xor_sync(0xffffffffu, rm, 8));
            rm = fmaxf(rm, __shfl_xor_sync(0xffffffffu, rm, 4));
            rm = fmaxf(rm, __shfl_xor_sync(0xffffffffu, rm, 2));
            rm = fmaxf(rm, __shfl_xor_sync(0xffffffffu, rm, 1));
            float mnew = fmaxf(m_r[i], rm);
            float a = __expf(m_r[i] - mnew);
            float rs = 0.f;
#pragma unroll
            for (int j = 0; j < 4; j++) { s[i][j] = __expf(s[i][j] - mnew); rs += s[i][j]; }
            rs += __shfl_xor_sync(0xffffffffu, rs, 8);
            rs += __shfl_xor_sync(0xffffffffu, rs, 4);
            rs += __shfl_xor_sync(0xffffffffu, rs, 2);
            rs += __shfl_xor_sync(0xffffffffu, rs, 1);
            l_r[i] = a * l_r[i] + rs;
            m_r[i] = mnew;
#pragma unroll
            for (int j = 0; j < 4; j++) o[i][j] *= a;
        }

        __syncthreads();  // all S reads of KPt done before overwriting with P^T
#pragma unroll
        for (int j = 0; j < 4; j++) {
            *(float4*)&KPt[(4 * tx + j) * LDP + 4 * ty] =
                make_float4(s[0][j], s[1][j], s[2][j], s[3][j]);
        }
        __syncthreads();

        // O += P * V : o[i][j] += Pt[c][4ty+i] * Vs[c][4tx+j]
#pragma unroll
        for (int c = 0; c < 64; c++) {
            float4 pp = *(const float4*)&KPt[c * LDP + 4 * ty];
            float4 vv = *(const float4*)&Vs[c * LDP + 4 * tx];
            o[0][0] += pp.x*vv.x; o[0][1] += pp.x*vv.y; o[0][2] += pp.x*vv.z; o[0][3] += pp.x*vv.w;
            o[1][0] += pp.y*vv.x; o[1][1] += pp.y*vv.y; o[1][2] += pp.y*vv.z; o[1][3] += pp.y*vv.w;
            o[2][0] += pp.z*vv.x; o[2][1] += pp.z*vv.y; o[2][2] += pp.z*vv.z; o[2][3] += pp.z*vv.w;
            o[3][0] += pp.w*vv.x; o[3][1] += pp.w*vv.y; o[3][2] += pp.w*vv.z; o[3][3] += pp.w*vv.w;
        }
    }

    // epilogue: O /= l, write [B,T,H,Dh]
#pragma unroll
    for (int i = 0; i < 4; i++) {
        float inv = 1.f / l_r[i];
        float4 w = make_float4(o[i][0] * inv, o[i][1] * inv, o[i][2] * inv, o[i][3] * inv);
        *(float4*)(OHg + base + (size_t)(q0 + 4 * ty + i) * PN + 4 * tx) = w;
    }
}

// ---------------- launch -----------------------------------------------------
extern "C" void kernel_launch(void* const* d_in, const int* in_sizes, int n_in,
                              void* d_out, int out_size) {
    const float* x  = (const float*)d_in[0];
    const float* WQ = (const float*)d_in[1];
    const float* bQ = (const float*)d_in[2];
    const float* WK = (const float*)d_in[3];
    const float* bK = (const float*)d_in[4];
    const float* WV = (const float*)d_in[5];
    const float* bV = (const float*)d_in[6];
    const float* WO = (const float*)d_in[7];
    const float* bO = (const float*)d_in[8];
    float* out = (float*)d_out;

    float *Q, *K, *V, *OH, *WOt;
    cudaGetSymbolAddress((void**)&Q,   g_Q);
    cudaGetSymbolAddress((void**)&K,   g_K);
    cudaGetSymbolAddress((void**)&V,   g_V);
    cudaGetSymbolAddress((void**)&OH,  g_OH);
    cudaGetSymbolAddress((void**)&WOt, g_WOt);

    const int flash_smem = 3 * 64 * LDP * (int)sizeof(float);  // 52224 B
    cudaFuncSetAttribute(flash_kernel, cudaFuncAttributeMaxDynamicSharedMemorySize,
                         flash_smem);

    dim3 gg(PN / 128, PM / 128);   // (8, 64)
    transpose_wo<<<(PD * PN) / 256, 256>>>(WO, WOt);
    gemm_nt_bias<<<gg, 256>>>(x, WQ, bQ, Q);
    gemm_nt_bias<<<gg, 256>>>(x, WK, bK, K);
    gemm_nt_bias<<<gg, 256>>>(x, WV, bV, V);
    flash_kernel<<<dim3(PT / 64, PB * PH), 256, flash_smem>>>(Q, K, V, OH);
    gemm_nt_bias<<<gg, 256>>>(OH, WOt, bO, out);
}

// round 5
// speedup vs baseline: 1.3279x; 1.3279x over previous
#include <cuda_runtime.h>
#include <cuda_bf16.h>
#include <cstdint>

// Problem constants (fixed shapes from reference)
#define PB 4
#define PT 2048
#define PD 1024
#define PH 16
#define PDH 64
#define PM (PB*PT)          // 8192 rows
#define PN 1024             // H*Dh == D
#define PK 1024

// ---------------- scratch (device globals; no allocations allowed) ----------
__device__ float g_Q [PM*PN];
__device__ float g_K [PM*PN];
__device__ float g_V [PM*PN];
__device__ float g_OH[PM*PN];
// bf16 split (hi/lo) operands for tensor-core GEMMs
__device__ __nv_bfloat16 g_xh [PM*PK], g_xl [PM*PK];
__device__ __nv_bfloat16 g_wqh[PN*PK], g_wql[PN*PK];
__device__ __nv_bfloat16 g_wkh[PN*PK], g_wkl[PN*PK];
__device__ __nv_bfloat16 g_wvh[PN*PK], g_wvl[PN*PK];
__device__ __nv_bfloat16 g_oth[PD*PN], g_otl[PD*PN];
__device__ __nv_bfloat16 g_ohh[PM*PN], g_ohl[PM*PN];

// ======================= PTX helpers (baseline sm_80+ features) =============
__device__ __forceinline__ uint32_t smem_to_u32(const void* p) {
    uint32_t a;
    asm("{ .reg .u64 t; cvta.to.shared.u64 t, %1; cvt.u32.u64 %0, t; }"
        : "=r"(a) : "l"(p));
    return a;
}
__device__ __forceinline__ void cp_async16(uint32_t dst, const void* src) {
    asm volatile("cp.async.cg.shared.global [%0], [%1], 16;"
                 :: "r"(dst), "l"(src) : "memory");
}
#define CP_COMMIT() asm volatile("cp.async.commit_group;" ::: "memory")
#define CP_WAIT0()  asm volatile("cp.async.wait_group 0;" ::: "memory")

__device__ __forceinline__ void ldsm_x4(uint32_t* r, uint32_t addr) {
    asm volatile("ldmatrix.sync.aligned.m8n8.x4.shared.b16 {%0,%1,%2,%3}, [%4];"
                 : "=r"(r[0]), "=r"(r[1]), "=r"(r[2]), "=r"(r[3]) : "r"(addr));
}
__device__ __forceinline__ void mma_bf16(float* d, const uint32_t* a, const uint32_t* b) {
    asm volatile("mma.sync.aligned.m16n8k16.row.col.f32.bf16.bf16.f32 "
                 "{%0,%1,%2,%3}, {%4,%5,%6,%7}, {%8,%9}, {%0,%1,%2,%3};"
                 : "+f"(d[0]), "+f"(d[1]), "+f"(d[2]), "+f"(d[3])
                 : "r"(a[0]), "r"(a[1]), "r"(a[2]), "r"(a[3]), "r"(b[0]), "r"(b[1]));
}

// ---------------- fp32 -> bf16 hi/lo split (vectorized x4) ------------------
__global__ __launch_bounds__(256)
void split_bf16(const float* __restrict__ in, __nv_bfloat16* __restrict__ hi,
                __nv_bfloat16* __restrict__ lo, int n4) {
    int i = blockIdx.x * 256 + threadIdx.x;
    if (i >= n4) return;
    float4 v = ((const float4*)in)[i];
    __nv_bfloat16 h0 = __float2bfloat16(v.x), h1 = __float2bfloat16(v.y);
    __nv_bfloat16 h2 = __float2bfloat16(v.z), h3 = __float2bfloat16(v.w);
    __nv_bfloat16 l0 = __float2bfloat16(v.x - __bfloat162float(h0));
    __nv_bfloat16 l1 = __float2bfloat16(v.y - __bfloat162float(h1));
    __nv_bfloat16 l2 = __float2bfloat16(v.z - __bfloat162float(h2));
    __nv_bfloat16 l3 = __float2bfloat16(v.w - __bfloat162float(h3));
    ((__nv_bfloat162*)hi)[2*i]   = __nv_bfloat162(h0, h1);
    ((__nv_bfloat162*)hi)[2*i+1] = __nv_bfloat162(h2, h3);
    ((__nv_bfloat162*)lo)[2*i]   = __nv_bfloat162(l0, l1);
    ((__nv_bfloat162*)lo)[2*i+1] = __nv_bfloat162(l2, l3);
}

// ---------------- WO transpose + split: [H][D][Dh] -> [D][H*Dh] hi/lo -------
__global__ void split_wot(const float* __restrict__ WO, __nv_bfloat16* __restrict__ hi,
                          __nv_bfloat16* __restrict__ lo) {
    int idx = blockIdx.x * 256 + threadIdx.x;
    int k = idx & 63;
    int d = (idx >> 6) & 1023;
    int h = idx >> 16;
    float v = WO[idx];
    __nv_bfloat16 hv = __float2bfloat16(v);
    __nv_bfloat16 lv = __float2bfloat16(v - __bfloat162float(hv));
    hi[d * 1024 + h * 64 + k] = hv;
    lo[d * 1024 + h * 64 + k] = lv;
}

// ---------------- split-bf16 NT GEMM + bias via mma.sync --------------------
// C[m][n] = sum_k A[m][k]*B[n][k] + bias[n]  ~=  AhBh + AhBl + AlBh
// CTA 128x128, BK=32, double-buffered cp.async stages, 8 warps of 64x32.
#define LDS_ROW 80                         // padded row: 32 bf16 = 64B -> 80B
#define TILE_B  (128 * LDS_ROW)            // 10240 per operand tile
#define STAGE_B (4 * TILE_B)               // Ah, Al, Bh, Bl
#define GEMM_SMEM (2 * STAGE_B)            // 81920

__global__ __launch_bounds__(256, 1)
void gemm_mma(const __nv_bfloat16* __restrict__ Ah, const __nv_bfloat16* __restrict__ Al,
              const __nv_bfloat16* __restrict__ Bh, const __nv_bfloat16* __restrict__ Bl,
              const float* __restrict__ bias, float* __restrict__ C) {
    extern __shared__ char sm_raw[];
    const uint32_t sbase = smem_to_u32(sm_raw);
    const int tid = threadIdx.x;
    const int lane = tid & 31, wid = tid >> 5;
    const int wm = wid & 1, wn = wid >> 1;            // warp grid 2(m) x 4(n)
    const int row0 = blockIdx.y * 128, col0 = blockIdx.x * 128;

    // loader mapping: each thread owns half a row (32B = 2x16B) of each tile
    const int lrow = tid >> 1, lhalf = tid & 1;
    const size_t aoff = (size_t)(row0 + lrow) * PK + lhalf * 16;
    const size_t boff = (size_t)(col0 + lrow) * PK + lhalf * 16;
    const uint32_t sdst = sbase + lrow * LDS_ROW + lhalf * 32;

    float acc[4][4][4];
#pragma unroll
    for (int i = 0; i < 4; i++)
#pragma unroll
        for (int j = 0; j < 4; j++)
#pragma unroll
            for (int v = 0; v < 4; v++) acc[i][j][v] = 0.f;

    // prologue: stage 0
    {
        const uint32_t st = sdst;
        cp_async16(st + 0*TILE_B,      Ah + aoff);
        cp_async16(st + 0*TILE_B + 16, Ah + aoff + 8);
        cp_async16(st + 1*TILE_B,      Al + aoff);
        cp_async16(st + 1*TILE_B + 16, Al + aoff + 8);
        cp_async16(st + 2*TILE_B,      Bh + boff);
        cp_async16(st + 2*TILE_B + 16, Bh + boff + 8);
        cp_async16(st + 3*TILE_B,      Bl + boff);
        cp_async16(st + 3*TILE_B + 16, Bl + boff + 8);
        CP_COMMIT();
    }

    const int NIT = PK / 32;   // 32
    for (int it = 0; it < NIT; it++) {
        const int s = it & 1;
        CP_WAIT0();
        __syncthreads();
        if (it + 1 < NIT) {
            const int k0 = (it + 1) * 32;
            const uint32_t st = sdst + ((it + 1) & 1) * STAGE_B;
            cp_async16(st + 0*TILE_B,      Ah + aoff + k0);
            cp_async16(st + 0*TILE_B + 16, Ah + aoff + k0 + 8);
            cp_async16(st + 1*TILE_B,      Al + aoff + k0);
            cp_async16(st + 1*TILE_B + 16, Al + aoff + k0 + 8);
            cp_async16(st + 2*TILE_B,      Bh + boff + k0);
            cp_async16(st + 2*TILE_B + 16, Bh + boff + k0 + 8);
            cp_async16(st + 3*TILE_B,      Bl + boff + k0);
            cp_async16(st + 3*TILE_B + 16, Bl + boff + k0 + 8);
            CP_COMMIT();
        }

        const uint32_t st = sbase + s * STAGE_B;
#pragma unroll
        for (int ks = 0; ks < 2; ks++) {                 // two k16 steps
            const uint32_t kb = ks * 32;                 // byte offset within row
            uint32_t ah[4][4], al[4][4];
#pragma unroll
            for (int mt = 0; mt < 4; mt++) {
                uint32_t addr = st +
                    (uint32_t)((wm * 64 + mt * 16 + (lane & 15)) * LDS_ROW) +
                    kb + ((lane >> 4) << 4);
                ldsm_x4(ah[mt], addr);                   // Ah tile
                ldsm_x4(al[mt], addr + TILE_B);          // Al tile
            }
            uint32_t bh[4][2], bl[4][2];
#pragma unroll
            for (int np = 0; np < 2; np++) {
                uint32_t addr = st + 2 * TILE_B +
                    (uint32_t)((wn * 32 + np * 16 + (lane & 7) + ((lane >> 4) << 3)) * LDS_ROW) +
                    (((lane >> 3) & 1) << 4) + kb;
                uint32_t r[4];
                ldsm_x4(r, addr);
                bh[2*np][0] = r[0]; bh[2*np][1] = r[1];
                bh[2*np+1][0] = r[2]; bh[2*np+1][1] = r[3];
                ldsm_x4(r, addr + TILE_B);
                bl[2*np][0] = r[0]; bl[2*np][1] = r[1];
                bl[2*np+1][0] = r[2]; bl[2*np+1][1] = r[3];
            }
#pragma unroll
            for (int mt = 0; mt < 4; mt++)
#pragma unroll
                for (int nt = 0; nt < 4; nt++) {
                    mma_bf16(acc[mt][nt], ah[mt], bh[nt]);
                    mma_bf16(acc[mt][nt], ah[mt], bl[nt]);
                    mma_bf16(acc[mt][nt], al[mt], bh[nt]);
                }
        }
    }

    // epilogue: fragment layout c0,c1=(row gid, col 2tig,2tig+1), c2,c3=row+8
    const int frow = lane >> 2, fcol = 2 * (lane & 3);
#pragma unroll
    for (int mt = 0; mt < 4; mt++) {
#pragma unroll
        for (int nt = 0; nt < 4; nt++) {
            const int gr = row0 + wm * 64 + mt * 16 + frow;
            const int gc = col0 + wn * 32 + nt * 8 + fcol;
            float2 bb = *(const float2*)(bias + gc);
            float2 v0 = make_float2(acc[mt][nt][0] + bb.x, acc[mt][nt][1] + bb.y);
            float2 v1 = make_float2(acc[mt][nt][2] + bb.x, acc[mt][nt][3] + bb.y);
            *(float2*)(C + (size_t)gr * PN + gc)       = v0;
            *(float2*)(C + (size_t)(gr + 8) * PN + gc) = v1;
        }
    }
}

// ---------------- flash attention (fp32 SIMT, proven in R3) -----------------
#define LDP 68
__global__ __launch_bounds__(256)
void flash_kernel(const float* __restrict__ Qg, const float* __restrict__ Kg,
                  const float* __restrict__ Vg, float* __restrict__ OHg) {
    extern __shared__ float sm[];
    float* Qt  = sm;
    float* KPt = sm + 64 * LDP;
    float* Vs  = sm + 2 * 64 * LDP;

    const int tid = threadIdx.x;
    const int tx = tid & 15, ty = tid >> 4;
    const int q0 = blockIdx.x * 64;
    const int bh = blockIdx.y;
    const int b = bh >> 4, h = bh & 15;
    const size_t base = (size_t)b * (PT * PN) + (size_t)h * PDH;

    const int lr  = tid >> 2;
    const int lc4 = tid & 3;

#pragma unroll
    for (int u = 0; u < 4; u++) {
        int c = (lc4 + 4 * u) * 4;
        float4 v = *(const float4*)(Qg + base + (size_t)(q0 + lr) * PN + c);
        Qt[(c + 0) * LDP + lr] = v.x * 0.125f;
        Qt[(c + 1) * LDP + lr] = v.y * 0.125f;
        Qt[(c + 2) * LDP + lr] = v.z * 0.125f;
        Qt[(c + 3) * LDP + lr] = v.w * 0.125f;
    }

    float m_r[4], l_r[4], o[4][4];
#pragma unroll
    for (int i = 0; i < 4; i++) {
        m_r[i] = -1e30f; l_r[i] = 0.f;
#pragma unroll
        for (int j = 0; j < 4; j++) o[i][j] = 0.f;
    }

    for (int c0 = 0; c0 < PT; c0 += 64) {
        __syncthreads();
#pragma unroll
        for (int u = 0; u < 4; u++) {
            int c = (lc4 + 4 * u) * 4;
            float4 kv = *(const float4*)(Kg + base + (size_t)(c0 + lr) * PN + c);
            KPt[(c + 0) * LDP + lr] = kv.x;
            KPt[(c + 1) * LDP + lr] = kv.y;
            KPt[(c + 2) * LDP + lr] = kv.z;
            KPt[(c + 3) * LDP + lr] = kv.w;
            float4 vv = *(const float4*)(Vg + base + (size_t)(c0 + lr) * PN + c);
            *(float4*)&Vs[lr * LDP + c] = vv;
        }
        __syncthreads();

        float s[4][4];
#pragma unroll
        for (int i = 0; i < 4; i++)
#pragma unroll
            for (int j = 0; j < 4; j++) s[i][j] = 0.f;
#pragma unroll
        for (int kk = 0; kk < 64; kk++) {
            float4 qa = *(const float4*)&Qt[kk * LDP + 4 * ty];
            float4 kb = *(const float4*)&KPt[kk * LDP + 4 * tx];
            s[0][0] += qa.x*kb.x; s[0][1] += qa.x*kb.y; s[0][2] += qa.x*kb.z; s[0][3] += qa.x*kb.w;
            s[1][0] += qa.y*kb.x; s[1][1] += qa.y*kb.y; s[1][2] += qa.y*kb.z; s[1][3] += qa.y*kb.w;
            s[2][0] += qa.z*kb.x; s[2][1] += qa.z*kb.y; s[2][2] += qa.z*kb.z; s[2][3] += qa.z*kb.w;
            s[3][0] += qa.w*kb.x; s[3][1] += qa.w*kb.y; s[3][2] += qa.w*kb.z; s[3][3] += qa.w*kb.w;
        }

#pragma unroll
        for (int i = 0; i < 4; i++) {
            float rm = fmaxf(fmaxf(s[i][0], s[i][1]), fmaxf(s[i][2], s[i][3]));
            rm = fmaxf(rm, __shfl_xor_sync(0xffffffffu, rm, 8));
            rm = fmaxf(rm, __shfl_xor_sync(0xffffffffu, rm, 4));
            rm = fmaxf(rm, __shfl_xor_sync(0xffffffffu, rm, 2));
            rm = fmaxf(rm, __shfl_xor_sync(0xffffffffu, rm, 1));
            float mnew = fmaxf(m_r[i], rm);
            float a = __expf(m_r[i] - mnew);
            float rs = 0.f;
#pragma unroll
            for (int j = 0; j < 4; j++) { s[i][j] = __expf(s[i][j] - mnew); rs += s[i][j]; }
            rs += __shfl_xor_sync(0xffffffffu, rs, 8);
            rs += __shfl_xor_sync(0xffffffffu, rs, 4);
            rs += __shfl_xor_sync(0xffffffffu, rs, 2);
            rs += __shfl_xor_sync(0xffffffffu, rs, 1);
            l_r[i] = a * l_r[i] + rs;
            m_r[i] = mnew;
#pragma unroll
            for (int j = 0; j < 4; j++) o[i][j] *= a;
        }

        __syncthreads();
#pragma unroll
        for (int j = 0; j < 4; j++) {
            *(float4*)&KPt[(4 * tx + j) * LDP + 4 * ty] =
                make_float4(s[0][j], s[1][j], s[2][j], s[3][j]);
        }
        __syncthreads();

#pragma unroll
        for (int c = 0; c < 64; c++) {
            float4 pp = *(const float4*)&KPt[c * LDP + 4 * ty];
            float4 vv = *(const float4*)&Vs[c * LDP + 4 * tx];
            o[0][0] += pp.x*vv.x; o[0][1] += pp.x*vv.y; o[0][2] += pp.x*vv.z; o[0][3] += pp.x*vv.w;
            o[1][0] += pp.y*vv.x; o[1][1] += pp.y*vv.y; o[1][2] += pp.y*vv.z; o[1][3] += pp.y*vv.w;
            o[2][0] += pp.z*vv.x; o[2][1] += pp.z*vv.y; o[2][2] += pp.z*vv.z; o[2][3] += pp.z*vv.w;
            o[3][0] += pp.w*vv.x; o[3][1] += pp.w*vv.y; o[3][2] += pp.w*vv.z; o[3][3] += pp.w*vv.w;
        }
    }

#pragma unroll
    for (int i = 0; i < 4; i++) {
        float inv = 1.f / l_r[i];
        float4 w = make_float4(o[i][0] * inv, o[i][1] * inv, o[i][2] * inv, o[i][3] * inv);
        *(float4*)(OHg + base + (size_t)(q0 + 4 * ty + i) * PN + 4 * tx) = w;
    }
}

// ---------------- launch -----------------------------------------------------
extern "C" void kernel_launch(void* const* d_in, const int* in_sizes, int n_in,
                              void* d_out, int out_size) {
    const float* x  = (const float*)d_in[0];
    const float* WQ = (const float*)d_in[1];
    const float* bQ = (const float*)d_in[2];
    const float* WK = (const float*)d_in[3];
    const float* bK = (const float*)d_in[4];
    const float* WV = (const float*)d_in[5];
    const float* bV = (const float*)d_in[6];
    const float* WO = (const float*)d_in[7];
    const float* bO = (const float*)d_in[8];
    float* out = (float*)d_out;

    float *Q, *K, *V, *OH;
    cudaGetSymbolAddress((void**)&Q,  g_Q);
    cudaGetSymbolAddress((void**)&K,  g_K);
    cudaGetSymbolAddress((void**)&V,  g_V);
    cudaGetSymbolAddress((void**)&OH, g_OH);
    __nv_bfloat16 *xh, *xl, *wqh, *wql, *wkh, *wkl, *wvh, *wvl, *oth, *otl, *ohh, *ohl;
    cudaGetSymbolAddress((void**)&xh,  g_xh);  cudaGetSymbolAddress((void**)&xl,  g_xl);
    cudaGetSymbolAddress((void**)&wqh, g_wqh); cudaGetSymbolAddress((void**)&wql, g_wql);
    cudaGetSymbolAddress((void**)&wkh, g_wkh); cudaGetSymbolAddress((void**)&wkl, g_wkl);
    cudaGetSymbolAddress((void**)&wvh, g_wvh); cudaGetSymbolAddress((void**)&wvl, g_wvl);
    cudaGetSymbolAddress((void**)&oth, g_oth); cudaGetSymbolAddress((void**)&otl, g_otl);
    cudaGetSymbolAddress((void**)&ohh, g_ohh); cudaGetSymbolAddress((void**)&ohl, g_ohl);

    const int flash_smem = 3 * 64 * LDP * (int)sizeof(float);  // 52224 B
    cudaFuncSetAttribute(flash_kernel, cudaFuncAttributeMaxDynamicSharedMemorySize,
                         flash_smem);
    cudaFuncSetAttribute(gemm_mma, cudaFuncAttributeMaxDynamicSharedMemorySize,
                         GEMM_SMEM);

    // fp32 -> bf16 hi/lo splits
    split_bf16<<<(PM * PK) / 1024, 256>>>(x,  xh,  xl,  (PM * PK) / 4);
    split_bf16<<<(PN * PK) / 1024, 256>>>(WQ, wqh, wql, (PN * PK) / 4);
    split_bf16<<<(PN * PK) / 1024, 256>>>(WK, wkh, wkl, (PN * PK) / 4);
    split_bf16<<<(PN * PK) / 1024, 256>>>(WV, wvh, wvl, (PN * PK) / 4);
    split_wot<<<(PD * PN) / 256, 256>>>(WO, oth, otl);

    dim3 gg(PN / 128, PM / 128);   // (8, 64)
    gemm_mma<<<gg, 256, GEMM_SMEM>>>(xh, xl, wqh, wql, bQ, Q);
    gemm_mma<<<gg, 256, GEMM_SMEM>>>(xh, xl, wkh, wkl, bK, K);
    gemm_mma<<<gg, 256, GEMM_SMEM>>>(xh, xl, wvh, wvl, bV, V);

    flash_kernel<<<dim3(PT / 64, PB * PH), 256, flash_smem>>>(Q, K, V, OH);

    split_bf16<<<(PM * PN) / 1024, 256>>>(OH, ohh, ohl, (PM * PN) / 4);
    gemm_mma<<<gg, 256, GEMM_SMEM>>>(ohh, ohl, oth, otl, bO, out);
}

// round 6
// speedup vs baseline: 2.6497x; 1.9954x over previous
#include <cuda_runtime.h>
#include <cuda_bf16.h>
#include <cstdint>

// Problem constants (fixed shapes from reference)
#define PB 4
#define PT 2048
#define PD 1024
#define PH 16
#define PDH 64
#define PM (PB*PT)          // 8192 rows
#define PN 1024             // H*Dh == D
#define PK 1024

// ---------------- scratch (device globals; no allocations allowed) ----------
__device__ __nv_bfloat16 g_xh [PM*PK], g_xl [PM*PK];
__device__ __nv_bfloat16 g_wqh[PN*PK], g_wql[PN*PK];
__device__ __nv_bfloat16 g_wkh[PN*PK], g_wkl[PN*PK];
__device__ __nv_bfloat16 g_wvh[PN*PK], g_wvl[PN*PK];
__device__ __nv_bfloat16 g_oth[PD*PN], g_otl[PD*PN];
__device__ __nv_bfloat16 g_qh [PM*PN], g_ql [PM*PN];
__device__ __nv_bfloat16 g_kh [PM*PN], g_kl [PM*PN];
__device__ __nv_bfloat16 g_vh [PM*PN], g_vl [PM*PN];
__device__ __nv_bfloat16 g_ohh[PM*PN], g_ohl[PM*PN];

// ======================= PTX helpers (baseline sm_80+ features) =============
__device__ __forceinline__ uint32_t smem_to_u32(const void* p) {
    uint32_t a;
    asm("{ .reg .u64 t; cvta.to.shared.u64 t, %1; cvt.u32.u64 %0, t; }"
        : "=r"(a) : "l"(p));
    return a;
}
__device__ __forceinline__ void cp_async16(uint32_t dst, const void* src) {
    asm volatile("cp.async.cg.shared.global [%0], [%1], 16;"
                 :: "r"(dst), "l"(src) : "memory");
}
#define CP_COMMIT() asm volatile("cp.async.commit_group;" ::: "memory")
#define CP_WAIT0()  asm volatile("cp.async.wait_group 0;" ::: "memory")

__device__ __forceinline__ void ldsm_x4(uint32_t* r, uint32_t addr) {
    asm volatile("ldmatrix.sync.aligned.m8n8.x4.shared.b16 {%0,%1,%2,%3}, [%4];"
                 : "=r"(r[0]), "=r"(r[1]), "=r"(r[2]), "=r"(r[3]) : "r"(addr));
}
__device__ __forceinline__ void ldsm_x4_t(uint32_t* r, uint32_t addr) {
    asm volatile("ldmatrix.sync.aligned.m8n8.x4.trans.shared.b16 {%0,%1,%2,%3}, [%4];"
                 : "=r"(r[0]), "=r"(r[1]), "=r"(r[2]), "=r"(r[3]) : "r"(addr));
}
__device__ __forceinline__ void mma_bf16(float* d, const uint32_t* a, const uint32_t* b) {
    asm volatile("mma.sync.aligned.m16n8k16.row.col.f32.bf16.bf16.f32 "
                 "{%0,%1,%2,%3}, {%4,%5,%6,%7}, {%8,%9}, {%0,%1,%2,%3};"
                 : "+f"(d[0]), "+f"(d[1]), "+f"(d[2]), "+f"(d[3])
                 : "r"(a[0]), "r"(a[1]), "r"(a[2]), "r"(a[3]), "r"(b[0]), "r"(b[1]));
}
__device__ __forceinline__ void splitpack2(float x, float y, uint32_t& hi, uint32_t& lo) {
    __nv_bfloat16 hx = __float2bfloat16(x), hy = __float2bfloat16(y);
    __nv_bfloat16 lx = __float2bfloat16(x - __bfloat162float(hx));
    __nv_bfloat16 ly = __float2bfloat16(y - __bfloat162float(hy));
    __nv_bfloat162 H(hx, hy), L(lx, ly);
    hi = *(uint32_t*)&H; lo = *(uint32_t*)&L;
}

// ---------------- fp32 -> bf16 hi/lo split (vectorized x4) ------------------
__global__ __launch_bounds__(256)
void split_bf16(const float* __restrict__ in, __nv_bfloat16* __restrict__ hi,
                __nv_bfloat16* __restrict__ lo, int n4) {
    int i = blockIdx.x * 256 + threadIdx.x;
    if (i >= n4) return;
    float4 v = ((const float4*)in)[i];
    __nv_bfloat16 h0 = __float2bfloat16(v.x), h1 = __float2bfloat16(v.y);
    __nv_bfloat16 h2 = __float2bfloat16(v.z), h3 = __float2bfloat16(v.w);
    __nv_bfloat16 l0 = __float2bfloat16(v.x - __bfloat162float(h0));
    __nv_bfloat16 l1 = __float2bfloat16(v.y - __bfloat162float(h1));
    __nv_bfloat16 l2 = __float2bfloat16(v.z - __bfloat162float(h2));
    __nv_bfloat16 l3 = __float2bfloat16(v.w - __bfloat162float(h3));
    ((__nv_bfloat162*)hi)[2*i]   = __nv_bfloat162(h0, h1);
    ((__nv_bfloat162*)hi)[2*i+1] = __nv_bfloat162(h2, h3);
    ((__nv_bfloat162*)lo)[2*i]   = __nv_bfloat162(l0, l1);
    ((__nv_bfloat162*)lo)[2*i+1] = __nv_bfloat162(l2, l3);
}

// ---------------- WO transpose + split: [H][D][Dh] -> [D][H*Dh] hi/lo -------
__global__ void split_wot(const float* __restrict__ WO, __nv_bfloat16* __restrict__ hi,
                          __nv_bfloat16* __restrict__ lo) {
    int idx = blockIdx.x * 256 + threadIdx.x;
    int k = idx & 63;
    int d = (idx >> 6) & 1023;
    int h = idx >> 16;
    float v = WO[idx];
    __nv_bfloat16 hv = __float2bfloat16(v);
    __nv_bfloat16 lv = __float2bfloat16(v - __bfloat162float(hv));
    hi[d * 1024 + h * 64 + k] = hv;
    lo[d * 1024 + h * 64 + k] = lv;
}

// ---------------- split-bf16 NT GEMM via mma.sync ---------------------------
// CTA 128x128, BK=32, double-buffered cp.async stages, 8 warps of 64x32.
#define LDS_ROW 80
#define TILE_B  (128 * LDS_ROW)
#define STAGE_B (4 * TILE_B)
#define GEMM_SMEM (2 * STAGE_B)

// mainloop shared by both epilogue variants
#define GEMM_BODY()                                                              \
    extern __shared__ char sm_raw[];                                             \
    const uint32_t sbase = smem_to_u32(sm_raw);                                  \
    const int tid = threadIdx.x;                                                 \
    const int lane = tid & 31, wid = tid >> 5;                                   \
    const int wm = wid & 1, wn = wid >> 1;                                       \
    const int row0 = blockIdx.y * 128, col0 = blockIdx.x * 128;                  \
    const int lrow = tid >> 1, lhalf = tid & 1;                                  \
    const size_t aoff = (size_t)(row0 + lrow) * PK + lhalf * 16;                 \
    const size_t boff = (size_t)(col0 + lrow) * PK + lhalf * 16;                 \
    const uint32_t sdst = sbase + lrow * LDS_ROW + lhalf * 32;                   \
    float acc[4][4][4];                                                          \
    _Pragma("unroll") for (int i = 0; i < 4; i++)                                \
    _Pragma("unroll") for (int j = 0; j < 4; j++)                                \
    _Pragma("unroll") for (int v = 0; v < 4; v++) acc[i][j][v] = 0.f;            \
    {                                                                            \
        const uint32_t st = sdst;                                                \
        cp_async16(st + 0*TILE_B,      Ah + aoff);                               \
        cp_async16(st + 0*TILE_B + 16, Ah + aoff + 8);                           \
        cp_async16(st + 1*TILE_B,      Al + aoff);                               \
        cp_async16(st + 1*TILE_B + 16, Al + aoff + 8);                           \
        cp_async16(st + 2*TILE_B,      Bh + boff);                               \
        cp_async16(st + 2*TILE_B + 16, Bh + boff + 8);                           \
        cp_async16(st + 3*TILE_B,      Bl + boff);                               \
        cp_async16(st + 3*TILE_B + 16, Bl + boff + 8);                           \
        CP_COMMIT();                                                             \
    }                                                                            \
    const int NIT = PK / 32;                                                     \
    for (int it = 0; it < NIT; it++) {                                           \
        const int s = it & 1;                                                    \
        CP_WAIT0();                                                              \
        __syncthreads();                                                         \
        if (it + 1 < NIT) {                                                      \
            const int k0 = (it + 1) * 32;                                        \
            const uint32_t st = sdst + ((it + 1) & 1) * STAGE_B;                 \
            cp_async16(st + 0*TILE_B,      Ah + aoff + k0);                      \
            cp_async16(st + 0*TILE_B + 16, Ah + aoff + k0 + 8);                  \
            cp_async16(st + 1*TILE_B,      Al + aoff + k0);                      \
            cp_async16(st + 1*TILE_B + 16, Al + aoff + k0 + 8);                  \
            cp_async16(st + 2*TILE_B,      Bh + boff + k0);                      \
            cp_async16(st + 2*TILE_B + 16, Bh + boff + k0 + 8);                  \
            cp_async16(st + 3*TILE_B,      Bl + boff + k0);                      \
            cp_async16(st + 3*TILE_B + 16, Bl + boff + k0 + 8);                  \
            CP_COMMIT();                                                         \
        }                                                                        \
        const uint32_t st = sbase + s * STAGE_B;                                 \
        _Pragma("unroll")                                                        \
        for (int ks = 0; ks < 2; ks++) {                                         \
            const uint32_t kb = ks * 32;                                         \
            uint32_t ah[4][4], al[4][4];                                         \
            _Pragma("unroll")                                                    \
            for (int mt = 0; mt < 4; mt++) {                                     \
                uint32_t addr = st +                                             \
                    (uint32_t)((wm * 64 + mt * 16 + (lane & 15)) * LDS_ROW) +    \
                    kb + ((lane >> 4) << 4);                                     \
                ldsm_x4(ah[mt], addr);                                           \
                ldsm_x4(al[mt], addr + TILE_B);                                  \
            }                                                                    \
            uint32_t bh[4][2], bl[4][2];                                         \
            _Pragma("unroll")                                                    \
            for (int np = 0; np < 2; np++) {                                     \
                uint32_t addr = st + 2 * TILE_B +                                \
                    (uint32_t)((wn * 32 + np * 16 + (lane & 7) + ((lane >> 4) << 3)) * LDS_ROW) + \
                    (((lane >> 3) & 1) << 4) + kb;                               \
                uint32_t r[4];                                                   \
                ldsm_x4(r, addr);                                                \
                bh[2*np][0] = r[0]; bh[2*np][1] = r[1];                          \
                bh[2*np+1][0] = r[2]; bh[2*np+1][1] = r[3];                      \
                ldsm_x4(r, addr + TILE_B);                                       \
                bl[2*np][0] = r[0]; bl[2*np][1] = r[1];                          \
                bl[2*np+1][0] = r[2]; bl[2*np+1][1] = r[3];                      \
            }                                                                    \
            _Pragma("unroll")                                                    \
            for (int mt = 0; mt < 4; mt++)                                       \
            _Pragma("unroll")                                                    \
                for (int nt = 0; nt < 4; nt++) {                                 \
                    mma_bf16(acc[mt][nt], ah[mt], bh[nt]);                       \
                    mma_bf16(acc[mt][nt], ah[mt], bl[nt]);                       \
                    mma_bf16(acc[mt][nt], al[mt], bh[nt]);                       \
                }                                                                \
        }                                                                        \
    }

// fp32-output variant (final O projection)
__global__ __launch_bounds__(256, 1)
void gemm_mma(const __nv_bfloat16* __restrict__ Ah, const __nv_bfloat16* __restrict__ Al,
              const __nv_bfloat16* __restrict__ Bh, const __nv_bfloat16* __restrict__ Bl,
              const float* __restrict__ bias, float* __restrict__ C) {
    GEMM_BODY()
    const int frow = lane >> 2, fcol = 2 * (lane & 3);
#pragma unroll
    for (int mt = 0; mt < 4; mt++) {
#pragma unroll
        for (int nt = 0; nt < 4; nt++) {
            const int gr = row0 + wm * 64 + mt * 16 + frow;
            const int gc = col0 + wn * 32 + nt * 8 + fcol;
            float2 bb = *(const float2*)(bias + gc);
            *(float2*)(C + (size_t)gr * PN + gc) =
                make_float2(acc[mt][nt][0] + bb.x, acc[mt][nt][1] + bb.y);
            *(float2*)(C + (size_t)(gr + 8) * PN + gc) =
                make_float2(acc[mt][nt][2] + bb.x, acc[mt][nt][3] + bb.y);
        }
    }
}

// bf16 hi/lo output variant (QKV projections; scale folds 1/sqrt(Dh) into Q)
__global__ __launch_bounds__(256, 1)
void gemm_mma_bf16out(const __nv_bfloat16* __restrict__ Ah, const __nv_bfloat16* __restrict__ Al,
                      const __nv_bfloat16* __restrict__ Bh, const __nv_bfloat16* __restrict__ Bl,
                      const float* __restrict__ bias,
                      __nv_bfloat16* __restrict__ Ch, __nv_bfloat16* __restrict__ Cl,
                      float scale) {
    GEMM_BODY()
    const int frow = lane >> 2, fcol = 2 * (lane & 3);
#pragma unroll
    for (int mt = 0; mt < 4; mt++) {
#pragma unroll
        for (int nt = 0; nt < 4; nt++) {
            const int gr = row0 + wm * 64 + mt * 16 + frow;
            const int gc = col0 + wn * 32 + nt * 8 + fcol;
            float2 bb = *(const float2*)(bias + gc);
            uint32_t h0, l0, h1, l1;
            splitpack2(scale * (acc[mt][nt][0] + bb.x), scale * (acc[mt][nt][1] + bb.y), h0, l0);
            splitpack2(scale * (acc[mt][nt][2] + bb.x), scale * (acc[mt][nt][3] + bb.y), h1, l1);
            *(uint32_t*)(Ch + (size_t)gr * PN + gc)       = h0;
            *(uint32_t*)(Cl + (size_t)gr * PN + gc)       = l0;
            *(uint32_t*)(Ch + (size_t)(gr + 8) * PN + gc) = h1;
            *(uint32_t*)(Cl + (size_t)(gr + 8) * PN + gc) = l1;
        }
    }
}

// ---------------- flash attention on tensor cores (split-bf16) --------------
// CTA: 128 queries, 8 warps (16 rows each), 64-key tiles, Dh=64.
// SMEM stage: Kh|Kl|Vh|Vl, each 64 rows x 128B, XOR-swizzled (c16 ^= row&7).
#define FLS_TILE  8192
#define FLS_STAGE 32768
#define FLS_SMEM  65536

__global__ __launch_bounds__(256, 1)
void flash_mma(const __nv_bfloat16* __restrict__ Qh, const __nv_bfloat16* __restrict__ Ql,
               const __nv_bfloat16* __restrict__ Kh, const __nv_bfloat16* __restrict__ Kl,
               const __nv_bfloat16* __restrict__ Vh, const __nv_bfloat16* __restrict__ Vl,
               __nv_bfloat16* __restrict__ Oh, __nv_bfloat16* __restrict__ Ol) {
    extern __shared__ char sm_raw[];
    const uint32_t sb = smem_to_u32(sm_raw);
    const int tid = threadIdx.x, lane = tid & 31, wid = tid >> 5;
    const int q0 = blockIdx.x * 128;
    const int b = blockIdx.y >> 4, h = blockIdx.y & 15;
    const size_t base = (size_t)b * (PT * PN) + (size_t)h * PDH;

    // ---- stage Q tile (hi at [0,16K), lo at [16K,32K)), swizzled
    {
        const int r = tid >> 1;
        const __nv_bfloat16* gqh = Qh + base + (size_t)(q0 + r) * PN;
        const __nv_bfloat16* gql = Ql + base + (size_t)(q0 + r) * PN;
        const uint32_t drow = sb + r * 128;
#pragma unroll
        for (int u = 0; u < 4; u++) {
            const int c16 = (tid & 1) * 4 + u;
            const uint32_t sw = (uint32_t)((c16 ^ (r & 7)) << 4);
            cp_async16(drow + sw,         gqh + c16 * 8);
            cp_async16(drow + 16384 + sw, gql + c16 * 8);
        }
    }
    CP_COMMIT(); CP_WAIT0();
    __syncthreads();

    // ---- extract Q fragments (A-operand, m16k16 per kstep)
    uint32_t qfh[4][4], qfl[4][4];
    {
        const int r = 16 * wid + (lane & 15);
        const uint32_t rowa = sb + r * 128;
#pragma unroll
        for (int t = 0; t < 4; t++) {
            const int c16 = 2 * t + (lane >> 4);
            const uint32_t a = rowa + (uint32_t)((c16 ^ (r & 7)) << 4);
            ldsm_x4(qfh[t], a);
            ldsm_x4(qfl[t], a + 16384);
        }
    }
    __syncthreads();

    // ---- K/V loader setup (4 threads per row, 2 chunks each)
    const int lr = tid >> 2;
    const int lc16 = 2 * (tid & 3);
    const __nv_bfloat16* gkh = Kh + base + (size_t)lr * PN + lc16 * 8;
    const __nv_bfloat16* gkl = Kl + base + (size_t)lr * PN + lc16 * 8;
    const __nv_bfloat16* gvh = Vh + base + (size_t)lr * PN + lc16 * 8;
    const __nv_bfloat16* gvl = Vl + base + (size_t)lr * PN + lc16 * 8;
    const uint32_t sw0 = (uint32_t)(((lc16 + 0) ^ (lr & 7)) << 4);
    const uint32_t sw1 = (uint32_t)(((lc16 + 1) ^ (lr & 7)) << 4);
    const uint32_t ldst = sb + lr * 128;

#define LOAD_STAGE(IT) do {                                                     \
        const uint32_t st_ = ldst + ((IT) & 1) * FLS_STAGE;                     \
        const size_t go_ = (size_t)(IT) * 64 * PN;                              \
        cp_async16(st_ +     0 + sw0, gkh + go_); cp_async16(st_ +     0 + sw1, gkh + go_ + 8); \
        cp_async16(st_ +  8192 + sw0, gkl + go_); cp_async16(st_ +  8192 + sw1, gkl + go_ + 8); \
        cp_async16(st_ + 16384 + sw0, gvh + go_); cp_async16(st_ + 16384 + sw1, gvh + go_ + 8); \
        cp_async16(st_ + 24576 + sw0, gvl + go_); cp_async16(st_ + 24576 + sw1, gvl + go_ + 8); \
        CP_COMMIT();                                                            \
    } while (0)

    LOAD_STAGE(0);

    float m0 = -1e30f, m1 = -1e30f, l0 = 0.f, l1 = 0.f;
    float o[8][4];
#pragma unroll
    for (int j = 0; j < 8; j++)
#pragma unroll
        for (int v = 0; v < 4; v++) o[j][v] = 0.f;

    const int NIT = PT / 64;   // 32
    for (int it = 0; it < NIT; it++) {
        CP_WAIT0();
        __syncthreads();
        if (it + 1 < NIT) LOAD_STAGE(it + 1);
        const uint32_t st = sb + (it & 1) * FLS_STAGE;

        // ---- S = Qh*Kh + Qh*Kl + Ql*Kh  (16x64 per warp)
        float s[8][4];
#pragma unroll
        for (int j = 0; j < 8; j++)
#pragma unroll
            for (int v = 0; v < 4; v++) s[j][v] = 0.f;
#pragma unroll
        for (int t = 0; t < 4; t++) {
#pragma unroll
            for (int np = 0; np < 4; np++) {
                const int row = np * 16 + (lane & 7) + ((lane >> 4) << 3);
                const int c16 = 2 * t + ((lane >> 3) & 1);
                const uint32_t a = st + row * 128 + (uint32_t)((c16 ^ (row & 7)) << 4);
                uint32_t kbh[4], kbl[4];
                ldsm_x4(kbh, a);
                ldsm_x4(kbl, a + 8192);
                mma_bf16(s[2*np],   qfh[t], kbh + 0);
                mma_bf16(s[2*np],   qfh[t], kbl + 0);
                mma_bf16(s[2*np],   qfl[t], kbh + 0);
                mma_bf16(s[2*np+1], qfh[t], kbh + 2);
                mma_bf16(s[2*np+1], qfh[t], kbl + 2);
                mma_bf16(s[2*np+1], qfl[t], kbh + 2);
            }
        }

        // ---- online softmax (rows lane>>2 and +8; quad shares a row)
        float rm0 = -1e30f, rm1 = -1e30f;
#pragma unroll
        for (int j = 0; j < 8; j++) {
            rm0 = fmaxf(rm0, fmaxf(s[j][0], s[j][1]));
            rm1 = fmaxf(rm1, fmaxf(s[j][2], s[j][3]));
        }
        rm0 = fmaxf(rm0, __shfl_xor_sync(0xffffffffu, rm0, 1));
        rm0 = fmaxf(rm0, __shfl_xor_sync(0xffffffffu, rm0, 2));
        rm1 = fmaxf(rm1, __shfl_xor_sync(0xffffffffu, rm1, 1));
        rm1 = fmaxf(rm1, __shfl_xor_sync(0xffffffffu, rm1, 2));
        const float mn0 = fmaxf(m0, rm0), mn1 = fmaxf(m1, rm1);
        const float al0 = __expf(m0 - mn0), al1 = __expf(m1 - mn1);
        float rs0 = 0.f, rs1 = 0.f;
#pragma unroll
        for (int j = 0; j < 8; j++) {
            s[j][0] = __expf(s[j][0] - mn0); rs0 += s[j][0];
            s[j][1] = __expf(s[j][1] - mn0); rs0 += s[j][1];
            s[j][2] = __expf(s[j][2] - mn1); rs1 += s[j][2];
            s[j][3] = __expf(s[j][3] - mn1); rs1 += s[j][3];
        }
        rs0 += __shfl_xor_sync(0xffffffffu, rs0, 1);
        rs0 += __shfl_xor_sync(0xffffffffu, rs0, 2);
        rs1 += __shfl_xor_sync(0xffffffffu, rs1, 1);
        rs1 += __shfl_xor_sync(0xffffffffu, rs1, 2);
        l0 = al0 * l0 + rs0; l1 = al1 * l1 + rs1;
        m0 = mn0; m1 = mn1;
#pragma unroll
        for (int j = 0; j < 8; j++) {
            o[j][0] *= al0; o[j][1] *= al0; o[j][2] *= al1; o[j][3] *= al1;
        }

        // ---- split P into bf16 hi/lo A-fragments (in registers)
        uint32_t pfh[4][4], pfl[4][4];
#pragma unroll
        for (int kt = 0; kt < 4; kt++) {
            splitpack2(s[2*kt][0],   s[2*kt][1],   pfh[kt][0], pfl[kt][0]);
            splitpack2(s[2*kt][2],   s[2*kt][3],   pfh[kt][1], pfl[kt][1]);
            splitpack2(s[2*kt+1][0], s[2*kt+1][1], pfh[kt][2], pfl[kt][2]);
            splitpack2(s[2*kt+1][2], s[2*kt+1][3], pfh[kt][3], pfl[kt][3]);
        }

        // ---- O += Ph*Vh + Ph*Vl + Pl*Vh
#pragma unroll
        for (int kt = 0; kt < 4; kt++) {
#pragma unroll
            for (int np = 0; np < 4; np++) {
                const int row = 16 * kt + (lane & 15);
                const int c16 = 2 * np + (lane >> 4);
                const uint32_t a = st + 16384 + row * 128 +
                                   (uint32_t)((c16 ^ (row & 7)) << 4);
                uint32_t vbh[4], vbl[4];
                ldsm_x4_t(vbh, a);
                ldsm_x4_t(vbl, a + 8192);
                mma_bf16(o[2*np],   pfh[kt], vbh + 0);
                mma_bf16(o[2*np],   pfh[kt], vbl + 0);
                mma_bf16(o[2*np],   pfl[kt], vbh + 0);
                mma_bf16(o[2*np+1], pfh[kt], vbh + 2);
                mma_bf16(o[2*np+1], pfh[kt], vbl + 2);
                mma_bf16(o[2*np+1], pfl[kt], vbh + 2);
            }
        }
    }

    // ---- epilogue: normalize, split to bf16 hi/lo, write [B,T,H,Dh]
    const float inv0 = 1.f / l0, inv1 = 1.f / l1;
    const int r0 = q0 + 16 * wid + (lane >> 2);
    const int c = 2 * (lane & 3);
#pragma unroll
    for (int j = 0; j < 8; j++) {
        const int gc = 8 * j + c;
        uint32_t h0, lo0, h1, lo1;
        splitpack2(o[j][0] * inv0, o[j][1] * inv0, h0, lo0);
        splitpack2(o[j][2] * inv1, o[j][3] * inv1, h1, lo1);
        *(uint32_t*)(Oh + base + (size_t)r0 * PN + gc)       = h0;
        *(uint32_t*)(Ol + base + (size_t)r0 * PN + gc)       = lo0;
        *(uint32_t*)(Oh + base + (size_t)(r0 + 8) * PN + gc) = h1;
        *(uint32_t*)(Ol + base + (size_t)(r0 + 8) * PN + gc) = lo1;
    }
}

// ---------------- launch -----------------------------------------------------
extern "C" void kernel_launch(void* const* d_in, const int* in_sizes, int n_in,
                              void* d_out, int out_size) {
    const float* x  = (const float*)d_in[0];
    const float* WQ = (const float*)d_in[1];
    const float* bQ = (const float*)d_in[2];
    const float* WK = (const float*)d_in[3];
    const float* bK = (const float*)d_in[4];
    const float* WV = (const float*)d_in[5];
    const float* bV = (const float*)d_in[6];
    const float* WO = (const float*)d_in[7];
    const float* bO = (const float*)d_in[8];
    float* out = (float*)d_out;

    __nv_bfloat16 *xh, *xl, *wqh, *wql, *wkh, *wkl, *wvh, *wvl, *oth, *otl;
    __nv_bfloat16 *qh, *ql, *kh, *kl, *vh, *vl, *ohh, *ohl;
    cudaGetSymbolAddress((void**)&xh,  g_xh);  cudaGetSymbolAddress((void**)&xl,  g_xl);
    cudaGetSymbolAddress((void**)&wqh, g_wqh); cudaGetSymbolAddress((void**)&wql, g_wql);
    cudaGetSymbolAddress((void**)&wkh, g_wkh); cudaGetSymbolAddress((void**)&wkl, g_wkl);
    cudaGetSymbolAddress((void**)&wvh, g_wvh); cudaGetSymbolAddress((void**)&wvl, g_wvl);
    cudaGetSymbolAddress((void**)&oth, g_oth); cudaGetSymbolAddress((void**)&otl, g_otl);
    cudaGetSymbolAddress((void**)&qh,  g_qh);  cudaGetSymbolAddress((void**)&ql,  g_ql);
    cudaGetSymbolAddress((void**)&kh,  g_kh);  cudaGetSymbolAddress((void**)&kl,  g_kl);
    cudaGetSymbolAddress((void**)&vh,  g_vh);  cudaGetSymbolAddress((void**)&vl,  g_vl);
    cudaGetSymbolAddress((void**)&ohh, g_ohh); cudaGetSymbolAddress((void**)&ohl, g_ohl);

    cudaFuncSetAttribute(gemm_mma, cudaFuncAttributeMaxDynamicSharedMemorySize, GEMM_SMEM);
    cudaFuncSetAttribute(gemm_mma_bf16out, cudaFuncAttributeMaxDynamicSharedMemorySize, GEMM_SMEM);
    cudaFuncSetAttribute(flash_mma, cudaFuncAttributeMaxDynamicSharedMemorySize, FLS_SMEM);

    // fp32 -> bf16 hi/lo splits (inputs + weights only)
    split_bf16<<<(PM * PK) / 1024, 256>>>(x,  xh,  xl,  (PM * PK) / 4);
    split_bf16<<<(PN * PK) / 1024, 256>>>(WQ, wqh, wql, (PN * PK) / 4);
    split_bf16<<<(PN * PK) / 1024, 256>>>(WK, wkh, wkl, (PN * PK) / 4);
    split_bf16<<<(PN * PK) / 1024, 256>>>(WV, wvh, wvl, (PN * PK) / 4);
    split_wot<<<(PD * PN) / 256, 256>>>(WO, oth, otl);

    dim3 gg(PN / 128, PM / 128);   // (8, 64)
    // QKV projections emit bf16 hi/lo directly; Q pre-scaled by 1/sqrt(Dh)=0.125
    gemm_mma_bf16out<<<gg, 256, GEMM_SMEM>>>(xh, xl, wqh, wql, bQ, qh, ql, 0.125f);
    gemm_mma_bf16out<<<gg, 256, GEMM_SMEM>>>(xh, xl, wkh, wkl, bK, kh, kl, 1.0f);
    gemm_mma_bf16out<<<gg, 256, GEMM_SMEM>>>(xh, xl, wvh, wvl, bV, vh, vl, 1.0f);

    flash_mma<<<dim3(PT / 128, PB * PH), 256, FLS_SMEM>>>(qh, ql, kh, kl, vh, vl, ohh, ohl);

    gemm_mma<<<gg, 256, GEMM_SMEM>>>(ohh, ohl, oth, otl, bO, out);
}

// round 7
// speedup vs baseline: 2.7304x; 1.0305x over previous
#include <cuda_runtime.h>
#include <cuda_bf16.h>
#include <cstdint>

// Problem constants (fixed shapes from reference)
#define PB 4
#define PT 2048
#define PD 1024
#define PH 16
#define PDH 64
#define PM (PB*PT)          // 8192 rows
#define PN 1024             // H*Dh == D
#define PK 1024

// ---------------- scratch (device globals; no allocations allowed) ----------
__device__ __nv_bfloat16 g_xh [PM*PK], g_xl [PM*PK];
__device__ __nv_bfloat16 g_wqh[PN*PK], g_wql[PN*PK];
__device__ __nv_bfloat16 g_wkh[PN*PK], g_wkl[PN*PK];
__device__ __nv_bfloat16 g_wvh[PN*PK], g_wvl[PN*PK];
__device__ __nv_bfloat16 g_oth[PD*PN], g_otl[PD*PN];
__device__ __nv_bfloat16 g_qh [PM*PN], g_ql [PM*PN];
__device__ __nv_bfloat16 g_kh [PM*PN], g_kl [PM*PN];
__device__ __nv_bfloat16 g_vh [PM*PN], g_vl [PM*PN];
__device__ __nv_bfloat16 g_ohh[PM*PN], g_ohl[PM*PN];

// ======================= PTX helpers (baseline sm_80+ features) =============
__device__ __forceinline__ uint32_t smem_to_u32(const void* p) {
    uint32_t a;
    asm("{ .reg .u64 t; cvta.to.shared.u64 t, %1; cvt.u32.u64 %0, t; }"
        : "=r"(a) : "l"(p));
    return a;
}
__device__ __forceinline__ void cp_async16(uint32_t dst, const void* src) {
    asm volatile("cp.async.cg.shared.global [%0], [%1], 16;"
                 :: "r"(dst), "l"(src) : "memory");
}
#define CP_COMMIT() asm volatile("cp.async.commit_group;" ::: "memory")
#define CP_WAIT0()  asm volatile("cp.async.wait_group 0;" ::: "memory")
#define CP_WAIT1()  asm volatile("cp.async.wait_group 1;" ::: "memory")
#define CP_WAIT2()  asm volatile("cp.async.wait_group 2;" ::: "memory")

__device__ __forceinline__ void ldsm_x4(uint32_t* r, uint32_t addr) {
    asm volatile("ldmatrix.sync.aligned.m8n8.x4.shared.b16 {%0,%1,%2,%3}, [%4];"
                 : "=r"(r[0]), "=r"(r[1]), "=r"(r[2]), "=r"(r[3]) : "r"(addr));
}
__device__ __forceinline__ void ldsm_x4_t(uint32_t* r, uint32_t addr) {
    asm volatile("ldmatrix.sync.aligned.m8n8.x4.trans.shared.b16 {%0,%1,%2,%3}, [%4];"
                 : "=r"(r[0]), "=r"(r[1]), "=r"(r[2]), "=r"(r[3]) : "r"(addr));
}
__device__ __forceinline__ void mma_bf16(float* d, const uint32_t* a, const uint32_t* b) {
    asm volatile("mma.sync.aligned.m16n8k16.row.col.f32.bf16.bf16.f32 "
                 "{%0,%1,%2,%3}, {%4,%5,%6,%7}, {%8,%9}, {%0,%1,%2,%3};"
                 : "+f"(d[0]), "+f"(d[1]), "+f"(d[2]), "+f"(d[3])
                 : "r"(a[0]), "r"(a[1]), "r"(a[2]), "r"(a[3]), "r"(b[0]), "r"(b[1]));
}
__device__ __forceinline__ void splitpack2(float x, float y, uint32_t& hi, uint32_t& lo) {
    __nv_bfloat16 hx = __float2bfloat16(x), hy = __float2bfloat16(y);
    __nv_bfloat16 lx = __float2bfloat16(x - __bfloat162float(hx));
    __nv_bfloat16 ly = __float2bfloat16(y - __bfloat162float(hy));
    __nv_bfloat162 H(hx, hy), L(lx, ly);
    hi = *(uint32_t*)&H; lo = *(uint32_t*)&L;
}

// ---------------- fp32 -> bf16 hi/lo split (vectorized x4) ------------------
__global__ __launch_bounds__(256)
void split_bf16(const float* __restrict__ in, __nv_bfloat16* __restrict__ hi,
                __nv_bfloat16* __restrict__ lo, int n4) {
    int i = blockIdx.x * 256 + threadIdx.x;
    if (i >= n4) return;
    float4 v = ((const float4*)in)[i];
    __nv_bfloat16 h0 = __float2bfloat16(v.x), h1 = __float2bfloat16(v.y);
    __nv_bfloat16 h2 = __float2bfloat16(v.z), h3 = __float2bfloat16(v.w);
    __nv_bfloat16 l0 = __float2bfloat16(v.x - __bfloat162float(h0));
    __nv_bfloat16 l1 = __float2bfloat16(v.y - __bfloat162float(h1));
    __nv_bfloat16 l2 = __float2bfloat16(v.z - __bfloat162float(h2));
    __nv_bfloat16 l3 = __float2bfloat16(v.w - __bfloat162float(h3));
    ((__nv_bfloat162*)hi)[2*i]   = __nv_bfloat162(h0, h1);
    ((__nv_bfloat162*)hi)[2*i+1] = __nv_bfloat162(h2, h3);
    ((__nv_bfloat162*)lo)[2*i]   = __nv_bfloat162(l0, l1);
    ((__nv_bfloat162*)lo)[2*i+1] = __nv_bfloat162(l2, l3);
}

// ---------------- WO transpose + split: [H][D][Dh] -> [D][H*Dh] hi/lo -------
__global__ void split_wot(const float* __restrict__ WO, __nv_bfloat16* __restrict__ hi,
                          __nv_bfloat16* __restrict__ lo) {
    int idx = blockIdx.x * 256 + threadIdx.x;
    int k = idx & 63;
    int d = (idx >> 6) & 1023;
    int h = idx >> 16;
    float v = WO[idx];
    __nv_bfloat16 hv = __float2bfloat16(v);
    __nv_bfloat16 lv = __float2bfloat16(v - __bfloat162float(hv));
    hi[d * 1024 + h * 64 + k] = hv;
    lo[d * 1024 + h * 64 + k] = lv;
}

// ---------------- split-bf16 NT GEMM via mma.sync ---------------------------
// CTA 128x128, BK=32, 3-stage cp.async pipeline (wait_group 1), 8 warps 64x32.
#define LDS_ROW 80
#define TILE_B  (128 * LDS_ROW)
#define STAGE_B (4 * TILE_B)
#define GEMM_SMEM (3 * STAGE_B)          // 122880

#define GEMM_LOAD(IT) do {                                                      \
        const int k0_ = (IT) * 32;                                              \
        const uint32_t st_ = sdst + (uint32_t)(((IT) % 3) * STAGE_B);           \
        cp_async16(st_ + 0*TILE_B,      Ah + aoff + k0_);                       \
        cp_async16(st_ + 0*TILE_B + 16, Ah + aoff + k0_ + 8);                   \
        cp_async16(st_ + 1*TILE_B,      Al + aoff + k0_);                       \
        cp_async16(st_ + 1*TILE_B + 16, Al + aoff + k0_ + 8);                   \
        cp_async16(st_ + 2*TILE_B,      Bh + boff + k0_);                       \
        cp_async16(st_ + 2*TILE_B + 16, Bh + boff + k0_ + 8);                   \
        cp_async16(st_ + 3*TILE_B,      Bl + boff + k0_);                       \
        cp_async16(st_ + 3*TILE_B + 16, Bl + boff + k0_ + 8);                   \
    } while (0)

#define GEMM_BODY()                                                              \
    extern __shared__ char sm_raw[];                                             \
    const uint32_t sbase = smem_to_u32(sm_raw);                                  \
    const int tid = threadIdx.x;                                                 \
    const int lane = tid & 31, wid = tid >> 5;                                   \
    const int wm = wid & 1, wn = wid >> 1;                                       \
    const int row0 = blockIdx.y * 128, col0 = blockIdx.x * 128;                  \
    const int lrow = tid >> 1, lhalf = tid & 1;                                  \
    const size_t aoff = (size_t)(row0 + lrow) * PK + lhalf * 16;                 \
    const size_t boff = (size_t)(col0 + lrow) * PK + lhalf * 16;                 \
    const uint32_t sdst = sbase + lrow * LDS_ROW + lhalf * 32;                   \
    float acc[4][4][4];                                                          \
    _Pragma("unroll") for (int i = 0; i < 4; i++)                                \
    _Pragma("unroll") for (int j = 0; j < 4; j++)                                \
    _Pragma("unroll") for (int v = 0; v < 4; v++) acc[i][j][v] = 0.f;            \
    GEMM_LOAD(0); CP_COMMIT();                                                   \
    GEMM_LOAD(1); CP_COMMIT();                                                   \
    const int NIT = PK / 32;                                                     \
    for (int it = 0; it < NIT; it++) {                                           \
        CP_WAIT1();                                                              \
        __syncthreads();                                                         \
        if (it + 2 < NIT) GEMM_LOAD(it + 2);                                     \
        CP_COMMIT();                                                             \
        const uint32_t st = sbase + (uint32_t)((it % 3) * STAGE_B);              \
        _Pragma("unroll")                                                        \
        for (int ks = 0; ks < 2; ks++) {                                         \
            const uint32_t kb = ks * 32;                                         \
            uint32_t ah[4][4], al[4][4];                                         \
            _Pragma("unroll")                                                    \
            for (int mt = 0; mt < 4; mt++) {                                     \
                uint32_t addr = st +                                             \
                    (uint32_t)((wm * 64 + mt * 16 + (lane & 15)) * LDS_ROW) +    \
                    kb + ((lane >> 4) << 4);                                     \
                ldsm_x4(ah[mt], addr);                                           \
                ldsm_x4(al[mt], addr + TILE_B);                                  \
            }                                                                    \
            uint32_t bh[4][2], bl[4][2];                                         \
            _Pragma("unroll")                                                    \
            for (int np = 0; np < 2; np++) {                                     \
                uint32_t addr = st + 2 * TILE_B +                                \
                    (uint32_t)((wn * 32 + np * 16 + (lane & 7) + ((lane >> 4) << 3)) * LDS_ROW) + \
                    (((lane >> 3) & 1) << 4) + kb;                               \
                uint32_t r[4];                                                   \
                ldsm_x4(r, addr);                                                \
                bh[2*np][0] = r[0]; bh[2*np][1] = r[1];                          \
                bh[2*np+1][0] = r[2]; bh[2*np+1][1] = r[3];                      \
                ldsm_x4(r, addr + TILE_B);                                       \
                bl[2*np][0] = r[0]; bl[2*np][1] = r[1];                          \
                bl[2*np+1][0] = r[2]; bl[2*np+1][1] = r[3];                      \
            }                                                                    \
            _Pragma("unroll")                                                    \
            for (int mt = 0; mt < 4; mt++)                                       \
            _Pragma("unroll")                                                    \
                for (int nt = 0; nt < 4; nt++) {                                 \
                    mma_bf16(acc[mt][nt], ah[mt], bh[nt]);                       \
                    mma_bf16(acc[mt][nt], ah[mt], bl[nt]);                       \
                    mma_bf16(acc[mt][nt], al[mt], bh[nt]);                       \
                }                                                                \
        }                                                                        \
    }

// fp32-output variant (final O projection)
__global__ __launch_bounds__(256, 1)
void gemm_mma(const __nv_bfloat16* __restrict__ Ah, const __nv_bfloat16* __restrict__ Al,
              const __nv_bfloat16* __restrict__ Bh, const __nv_bfloat16* __restrict__ Bl,
              const float* __restrict__ bias, float* __restrict__ C) {
    GEMM_BODY()
    const int frow = lane >> 2, fcol = 2 * (lane & 3);
#pragma unroll
    for (int mt = 0; mt < 4; mt++) {
#pragma unroll
        for (int nt = 0; nt < 4; nt++) {
            const int gr = row0 + wm * 64 + mt * 16 + frow;
            const int gc = col0 + wn * 32 + nt * 8 + fcol;
            float2 bb = *(const float2*)(bias + gc);
            *(float2*)(C + (size_t)gr * PN + gc) =
                make_float2(acc[mt][nt][0] + bb.x, acc[mt][nt][1] + bb.y);
            *(float2*)(C + (size_t)(gr + 8) * PN + gc) =
                make_float2(acc[mt][nt][2] + bb.x, acc[mt][nt][3] + bb.y);
        }
    }
}

// fused QKV: blockIdx.z selects weight/bias/output; Q pre-scaled by 0.125
__global__ __launch_bounds__(256, 1)
void gemm_qkv(const __nv_bfloat16* __restrict__ Ah, const __nv_bfloat16* __restrict__ Al,
              const __nv_bfloat16* __restrict__ wqh, const __nv_bfloat16* __restrict__ wql,
              const __nv_bfloat16* __restrict__ wkh, const __nv_bfloat16* __restrict__ wkl,
              const __nv_bfloat16* __restrict__ wvh, const __nv_bfloat16* __restrict__ wvl,
              const float* __restrict__ bQ, const float* __restrict__ bK,
              const float* __restrict__ bV,
              __nv_bfloat16* __restrict__ qh, __nv_bfloat16* __restrict__ ql,
              __nv_bfloat16* __restrict__ kh, __nv_bfloat16* __restrict__ kl,
              __nv_bfloat16* __restrict__ vh, __nv_bfloat16* __restrict__ vl) {
    const int z = blockIdx.z;
    const __nv_bfloat16* Bh = (z == 0) ? wqh : (z == 1) ? wkh : wvh;
    const __nv_bfloat16* Bl = (z == 0) ? wql : (z == 1) ? wkl : wvl;
    const float* bias = (z == 0) ? bQ : (z == 1) ? bK : bV;
    __nv_bfloat16* Ch = (z == 0) ? qh : (z == 1) ? kh : vh;
    __nv_bfloat16* Cl = (z == 0) ? ql : (z == 1) ? kl : vl;
    const float scale = (z == 0) ? 0.125f : 1.0f;
    GEMM_BODY()
    const int frow = lane >> 2, fcol = 2 * (lane & 3);
#pragma unroll
    for (int mt = 0; mt < 4; mt++) {
#pragma unroll
        for (int nt = 0; nt < 4; nt++) {
            const int gr = row0 + wm * 64 + mt * 16 + frow;
            const int gc = col0 + wn * 32 + nt * 8 + fcol;
            float2 bb = *(const float2*)(bias + gc);
            uint32_t h0, l0, h1, l1;
            splitpack2(scale * (acc[mt][nt][0] + bb.x), scale * (acc[mt][nt][1] + bb.y), h0, l0);
            splitpack2(scale * (acc[mt][nt][2] + bb.x), scale * (acc[mt][nt][3] + bb.y), h1, l1);
            *(uint32_t*)(Ch + (size_t)gr * PN + gc)       = h0;
            *(uint32_t*)(Cl + (size_t)gr * PN + gc)       = l0;
            *(uint32_t*)(Ch + (size_t)(gr + 8) * PN + gc) = h1;
            *(uint32_t*)(Cl + (size_t)(gr + 8) * PN + gc) = l1;
        }
    }
}

// ---------------- flash attention on tensor cores (split-bf16) --------------
// CTA: 128 queries, 8 warps, 64-key tiles, Dh=64. 3-stage KV pipeline.
// SMEM: Q hi/lo [0,32K); KV stages at 32K + s*32K (Kh|Kl|Vh|Vl, swizzled).
#define FLS_STAGE 32768
#define FLS_QB    32768
#define FLS_SMEM  (FLS_QB + 3 * FLS_STAGE)   // 131072

__global__ __launch_bounds__(256, 1)
void flash_mma(const __nv_bfloat16* __restrict__ Qh, const __nv_bfloat16* __restrict__ Ql,
               const __nv_bfloat16* __restrict__ Kh, const __nv_bfloat16* __restrict__ Kl,
               const __nv_bfloat16* __restrict__ Vh, const __nv_bfloat16* __restrict__ Vl,
               __nv_bfloat16* __restrict__ Oh, __nv_bfloat16* __restrict__ Ol) {
    extern __shared__ char sm_raw[];
    const uint32_t sb = smem_to_u32(sm_raw);
    const int tid = threadIdx.x, lane = tid & 31, wid = tid >> 5;
    const int q0 = blockIdx.x * 128;
    const int b = blockIdx.y >> 4, h = blockIdx.y & 15;
    const size_t base = (size_t)b * (PT * PN) + (size_t)h * PDH;

    // ---- K/V loader setup (4 threads per row, 2 chunks each)
    const int lr = tid >> 2;
    const int lc16 = 2 * (tid & 3);
    const __nv_bfloat16* gkh = Kh + base + (size_t)lr * PN + lc16 * 8;
    const __nv_bfloat16* gkl = Kl + base + (size_t)lr * PN + lc16 * 8;
    const __nv_bfloat16* gvh = Vh + base + (size_t)lr * PN + lc16 * 8;
    const __nv_bfloat16* gvl = Vl + base + (size_t)lr * PN + lc16 * 8;
    const uint32_t sw0 = (uint32_t)(((lc16 + 0) ^ (lr & 7)) << 4);
    const uint32_t sw1 = (uint32_t)(((lc16 + 1) ^ (lr & 7)) << 4);
    const uint32_t ldkv = sb + FLS_QB + lr * 128;

#define LOAD_STAGE(IT) do {                                                     \
        const uint32_t st_ = ldkv + (uint32_t)(((IT) % 3) * FLS_STAGE);         \
        const size_t go_ = (size_t)(IT) * 64 * PN;                              \
        cp_async16(st_ +     0 + sw0, gkh + go_); cp_async16(st_ +     0 + sw1, gkh + go_ + 8); \
        cp_async16(st_ +  8192 + sw0, gkl + go_); cp_async16(st_ +  8192 + sw1, gkl + go_ + 8); \
        cp_async16(st_ + 16384 + sw0, gvh + go_); cp_async16(st_ + 16384 + sw1, gvh + go_ + 8); \
        cp_async16(st_ + 24576 + sw0, gvl + go_); cp_async16(st_ + 24576 + sw1, gvl + go_ + 8); \
    } while (0)

    // ---- stage Q tile (hi at [0,16K), lo at [16K,32K)), swizzled; then KV 0/1
    {
        const int r = tid >> 1;
        const __nv_bfloat16* gqh = Qh + base + (size_t)(q0 + r) * PN;
        const __nv_bfloat16* gql = Ql + base + (size_t)(q0 + r) * PN;
        const uint32_t drow = sb + r * 128;
#pragma unroll
        for (int u = 0; u < 4; u++) {
            const int c16 = (tid & 1) * 4 + u;
            const uint32_t sw = (uint32_t)((c16 ^ (r & 7)) << 4);
            cp_async16(drow + sw,         gqh + c16 * 8);
            cp_async16(drow + 16384 + sw, gql + c16 * 8);
        }
    }
    CP_COMMIT();
    LOAD_STAGE(0); CP_COMMIT();
    LOAD_STAGE(1); CP_COMMIT();

    // ---- wait for Q only, extract Q fragments (A-operand, m16k16 per kstep)
    CP_WAIT2();
    __syncthreads();
    uint32_t qfh[4][4], qfl[4][4];
    {
        const int r = 16 * wid + (lane & 15);
        const uint32_t rowa = sb + r * 128;
#pragma unroll
        for (int t = 0; t < 4; t++) {
            const int c16 = 2 * t + (lane >> 4);
            const uint32_t a = rowa + (uint32_t)((c16 ^ (r & 7)) << 4);
            ldsm_x4(qfh[t], a);
            ldsm_x4(qfl[t], a + 16384);
        }
    }

    float m0 = -1e30f, m1 = -1e30f, l0 = 0.f, l1 = 0.f;
    float o[8][4];
#pragma unroll
    for (int j = 0; j < 8; j++)
#pragma unroll
        for (int v = 0; v < 4; v++) o[j][v] = 0.f;

    const int NIT = PT / 64;   // 32
    for (int it = 0; it < NIT; it++) {
        CP_WAIT1();
        __syncthreads();
        if (it + 2 < NIT) LOAD_STAGE(it + 2);
        CP_COMMIT();
        const uint32_t st = sb + FLS_QB + (uint32_t)((it % 3) * FLS_STAGE);

        // ---- S = Qh*Kh + Qh*Kl + Ql*Kh  (16x64 per warp)
        float s[8][4];
#pragma unroll
        for (int j = 0; j < 8; j++)
#pragma unroll
            for (int v = 0; v < 4; v++) s[j][v] = 0.f;
#pragma unroll
        for (int t = 0; t < 4; t++) {
#pragma unroll
            for (int np = 0; np < 4; np++) {
                const int row = np * 16 + (lane & 7) + ((lane >> 4) << 3);
                const int c16 = 2 * t + ((lane >> 3) & 1);
                const uint32_t a = st + row * 128 + (uint32_t)((c16 ^ (row & 7)) << 4);
                uint32_t kbh[4], kbl[4];
                ldsm_x4(kbh, a);
                ldsm_x4(kbl, a + 8192);
                mma_bf16(s[2*np],   qfh[t], kbh + 0);
                mma_bf16(s[2*np],   qfh[t], kbl + 0);
                mma_bf16(s[2*np],   qfl[t], kbh + 0);
                mma_bf16(s[2*np+1], qfh[t], kbh + 2);
                mma_bf16(s[2*np+1], qfh[t], kbl + 2);
                mma_bf16(s[2*np+1], qfl[t], kbh + 2);
            }
        }

        // ---- online softmax (rows lane>>2 and +8; quad shares a row)
        float rm0 = -1e30f, rm1 = -1e30f;
#pragma unroll
        for (int j = 0; j < 8; j++) {
            rm0 = fmaxf(rm0, fmaxf(s[j][0], s[j][1]));
            rm1 = fmaxf(rm1, fmaxf(s[j][2], s[j][3]));
        }
        rm0 = fmaxf(rm0, __shfl_xor_sync(0xffffffffu, rm0, 1));
        rm0 = fmaxf(rm0, __shfl_xor_sync(0xffffffffu, rm0, 2));
        rm1 = fmaxf(rm1, __shfl_xor_sync(0xffffffffu, rm1, 1));
        rm1 = fmaxf(rm1, __shfl_xor_sync(0xffffffffu, rm1, 2));
        const float mn0 = fmaxf(m0, rm0), mn1 = fmaxf(m1, rm1);
        const float al0 = __expf(m0 - mn0), al1 = __expf(m1 - mn1);
        float rs0 = 0.f, rs1 = 0.f;
#pragma unroll
        for (int j = 0; j < 8; j++) {
            s[j][0] = __expf(s[j][0] - mn0); rs0 += s[j][0];
            s[j][1] = __expf(s[j][1] - mn0); rs0 += s[j][1];
            s[j][2] = __expf(s[j][2] - mn1); rs1 += s[j][2];
            s[j][3] = __expf(s[j][3] - mn1); rs1 += s[j][3];
        }
        rs0 += __shfl_xor_sync(0xffffffffu, rs0, 1);
        rs0 += __shfl_xor_sync(0xffffffffu, rs0, 2);
        rs1 += __shfl_xor_sync(0xffffffffu, rs1, 1);
        rs1 += __shfl_xor_sync(0xffffffffu, rs1, 2);
        l0 = al0 * l0 + rs0; l1 = al1 * l1 + rs1;
        m0 = mn0; m1 = mn1;
#pragma unroll
        for (int j = 0; j < 8; j++) {
            o[j][0] *= al0; o[j][1] *= al0; o[j][2] *= al1; o[j][3] *= al1;
        }

        // ---- split P into bf16 hi/lo A-fragments (in registers)
        uint32_t pfh[4][4], pfl[4][4];
#pragma unroll
        for (int kt = 0; kt < 4; kt++) {
            splitpack2(s[2*kt][0],   s[2*kt][1],   pfh[kt][0], pfl[kt][0]);
            splitpack2(s[2*kt][2],   s[2*kt][3],   pfh[kt][1], pfl[kt][1]);
            splitpack2(s[2*kt+1][0], s[2*kt+1][1], pfh[kt][2], pfl[kt][2]);
            splitpack2(s[2*kt+1][2], s[2*kt+1][3], pfh[kt][3], pfl[kt][3]);
        }

        // ---- O += Ph*Vh + Ph*Vl + Pl*Vh
#pragma unroll
        for (int kt = 0; kt < 4; kt++) {
#pragma unroll
            for (int np = 0; np < 4; np++) {
                const int row = 16 * kt + (lane & 15);
                const int c16 = 2 * np + (lane >> 4);
                const uint32_t a = st + 16384 + row * 128 +
                                   (uint32_t)((c16 ^ (row & 7)) << 4);
                uint32_t vbh[4], vbl[4];
                ldsm_x4_t(vbh, a);
                ldsm_x4_t(vbl, a + 8192);
                mma_bf16(o[2*np],   pfh[kt], vbh + 0);
                mma_bf16(o[2*np],   pfh[kt], vbl + 0);
                mma_bf16(o[2*np],   pfl[kt], vbh + 0);
                mma_bf16(o[2*np+1], pfh[kt], vbh + 2);
                mma_bf16(o[2*np+1], pfh[kt], vbl + 2);
                mma_bf16(o[2*np+1], pfl[kt], vbh + 2);
            }
        }
    }

    // ---- epilogue: normalize, split to bf16 hi/lo, write [B,T,H,Dh]
    const float inv0 = 1.f / l0, inv1 = 1.f / l1;
    const int r0 = q0 + 16 * wid + (lane >> 2);
    const int c = 2 * (lane & 3);
#pragma unroll
    for (int j = 0; j < 8; j++) {
        const int gc = 8 * j + c;
        uint32_t h0, lo0, h1, lo1;
        splitpack2(o[j][0] * inv0, o[j][1] * inv0, h0, lo0);
        splitpack2(o[j][2] * inv1, o[j][3] * inv1, h1, lo1);
        *(uint32_t*)(Oh + base + (size_t)r0 * PN + gc)       = h0;
        *(uint32_t*)(Ol + base + (size_t)r0 * PN + gc)       = lo0;
        *(uint32_t*)(Oh + base + (size_t)(r0 + 8) * PN + gc) = h1;
        *(uint32_t*)(Ol + base + (size_t)(r0 + 8) * PN + gc) = lo1;
    }
}

// ---------------- launch -----------------------------------------------------
extern "C" void kernel_launch(void* const* d_in, const int* in_sizes, int n_in,
                              void* d_out, int out_size) {
    const float* x  = (const float*)d_in[0];
    const float* WQ = (const float*)d_in[1];
    const float* bQ = (const float*)d_in[2];
    const float* WK = (const float*)d_in[3];
    const float* bK = (const float*)d_in[4];
    const float* WV = (const float*)d_in[5];
    const float* bV = (const float*)d_in[6];
    const float* WO = (const float*)d_in[7];
    const float* bO = (const float*)d_in[8];
    float* out = (float*)d_out;

    __nv_bfloat16 *xh, *xl, *wqh, *wql, *wkh, *wkl, *wvh, *wvl, *oth, *otl;
    __nv_bfloat16 *qh, *ql, *kh, *kl, *vh, *vl, *ohh, *ohl;
    cudaGetSymbolAddress((void**)&xh,  g_xh);  cudaGetSymbolAddress((void**)&xl,  g_xl);
    cudaGetSymbolAddress((void**)&wqh, g_wqh); cudaGetSymbolAddress((void**)&wql, g_wql);
    cudaGetSymbolAddress((void**)&wkh, g_wkh); cudaGetSymbolAddress((void**)&wkl, g_wkl);
    cudaGetSymbolAddress((void**)&wvh, g_wvh); cudaGetSymbolAddress((void**)&wvl, g_wvl);
    cudaGetSymbolAddress((void**)&oth, g_oth); cudaGetSymbolAddress((void**)&otl, g_otl);
    cudaGetSymbolAddress((void**)&qh,  g_qh);  cudaGetSymbolAddress((void**)&ql,  g_ql);
    cudaGetSymbolAddress((void**)&kh,  g_kh);  cudaGetSymbolAddress((void**)&kl,  g_kl);
    cudaGetSymbolAddress((void**)&vh,  g_vh);  cudaGetSymbolAddress((void**)&vl,  g_vl);
    cudaGetSymbolAddress((void**)&ohh, g_ohh); cudaGetSymbolAddress((void**)&ohl, g_ohl);

    cudaFuncSetAttribute(gemm_mma, cudaFuncAttributeMaxDynamicSharedMemorySize, GEMM_SMEM);
    cudaFuncSetAttribute(gemm_qkv, cudaFuncAttributeMaxDynamicSharedMemorySize, GEMM_SMEM);
    cudaFuncSetAttribute(flash_mma, cudaFuncAttributeMaxDynamicSharedMemorySize, FLS_SMEM);

    // fp32 -> bf16 hi/lo splits (inputs + weights only)
    split_bf16<<<(PM * PK) / 1024, 256>>>(x,  xh,  xl,  (PM * PK) / 4);
    split_bf16<<<(PN * PK) / 1024, 256>>>(WQ, wqh, wql, (PN * PK) / 4);
    split_bf16<<<(PN * PK) / 1024, 256>>>(WK, wkh, wkl, (PN * PK) / 4);
    split_bf16<<<(PN * PK) / 1024, 256>>>(WV, wvh, wvl, (PN * PK) / 4);
    split_wot<<<(PD * PN) / 256, 256>>>(WO, oth, otl);

    // fused QKV projections (z selects head matrix); Q pre-scaled by 0.125
    gemm_qkv<<<dim3(PN / 128, PM / 128, 3), 256, GEMM_SMEM>>>(
        xh, xl, wqh, wql, wkh, wkl, wvh, wvl, bQ, bK, bV,
        qh, ql, kh, kl, vh, vl);

    flash_mma<<<dim3(PT / 128, PB * PH), 256, FLS_SMEM>>>(qh, ql, kh, kl, vh, vl, ohh, ohl);

    gemm_mma<<<dim3(PN / 128, PM / 128), 256, GEMM_SMEM>>>(ohh, ohl, oth, otl, bO, out);
}